// round 10
// baseline (speedup 1.0000x reference)
#include <cuda_runtime.h>

#define Lf 512
#define Bf 4096
#define Tt 25
#define NP 13      // i-pairs (2p, 2p+1); slot p=12 hi half = pad (i=25)
#define GST 32     // g_score row stride (128B-aligned rows)
#define FWPB 5     // warps per block in fwd kernel

__device__ float g_score[(size_t)Lf * Bf * GST];
__device__ float g_logz[Bf];
__device__ float g_num[Bf];

typedef unsigned long long u64;

__device__ __forceinline__ u64 pack2(float lo, float hi) {
    u64 r; asm("mov.b64 %0,{%1,%2};" : "=l"(r) : "f"(lo), "f"(hi)); return r;
}
__device__ __forceinline__ void un2(u64 v, float& a, float& b) {
    asm("mov.b64 {%0,%1},%2;" : "=f"(a), "=f"(b) : "l"(v));
}
__device__ __forceinline__ u64 fma2(u64 a, u64 b, u64 c) {
    u64 d; asm("fma.rn.f32x2 %0,%1,%2,%3;" : "=l"(d) : "l"(a), "l"(b), "l"(c)); return d;
}
__device__ __forceinline__ u64 add2(u64 a, u64 b) {
    u64 d; asm("add.rn.f32x2 %0,%1,%2;" : "=l"(d) : "l"(a), "l"(b)); return d;
}
__device__ __forceinline__ unsigned ford(float f) {
    unsigned v = __float_as_uint(f);
    return (v & 0x80000000u) ? ~v : (v | 0x80000000u);
}
__device__ __forceinline__ float rcpa(float x) {
    float r; asm("rcp.approx.f32 %0, %1;" : "=f"(r) : "f"(x)); return r;
}

// ---------------------------------------------------------------------------
__global__ void init_kernel(float* out, int base) {
    int i = blockIdx.x * blockDim.x + threadIdx.x;
    if (i < Bf) g_num[i] = 0.f;
    if (i == 0 && base > 0) out[0] = 0.f;
}

// ---------------------------------------------------------------------------
// One fused forward+Viterbi step. State (a,v) published to this step's smem
// buffer, then all 13 packed pairs read back broadcast (LDS.128).
__device__ __forceinline__ void fwd_step(
    float* sw, int sp4sh,               // buffer base + this lane's write slot
    const u64* Ep, const u64* Tp,
    float& a, float& v, float& inv,
    float e_cur, float ee_cur,
    float& logacc2, bool act, float*& gsp)
{
    sw[sp4sh] = a;
    sw[sp4sh + 2] = v;
    __syncwarp();

    const ulonglong2* ps = (const ulonglong2*)sw;
    u64 re = 0ull, ro = 0ull;
    float m0 = -1e30f, m1 = -1e30f, m2 = -1e30f, m3 = -1e30f;
#pragma unroll
    for (int p = 0; p < NP; p++) {
        ulonglong2 s2 = ps[p];               // {a-pair, v-pair} broadcast
        float sx, sy;
        if (p & 1) {
            ro = fma2(s2.x, Ep[p], ro);
            un2(add2(s2.y, Tp[p]), sx, sy);
            m2 = fmaxf(m2, sx); m3 = fmaxf(m3, sy);
        } else {
            re = fma2(s2.x, Ep[p], re);
            un2(add2(s2.y, Tp[p]), sx, sy);
            m0 = fmaxf(m0, sx); m1 = fmaxf(m1, sy);
        }
    }
    float rx, ry; un2(add2(re, ro), rx, ry);
    float u  = (rx + ry) * ee_cur * inv;
    float sv = fmaxf(fmaxf(m0, m1), fmaxf(m2, m3)) + e_cur;  // exact (monotone)

    logacc2 -= __log2f(inv);                 // account applied scale, off-path

    a = act ? u : 0.f;
    v = act ? sv : -1e30f;
    if (act) *gsp = sv;
    gsp += (size_t)Bf * GST;

    inv = __shfl_sync(0xffffffffu, rcpa(u), 0);   // scale for NEXT step
}

// Fused forward + Viterbi: ONE chain per warp (4096 warps -> ~6.3 warps/SMSP).
// Lane j owns tag column j; state broadcast via per-warp smem buffers.
__global__ __launch_bounds__(32 * FWPB, 5) void fwd_vit_kernel(
    const float* __restrict__ em, const float* __restrict__ trans,
    const float* __restrict__ start, const float* __restrict__ endt)
{
    // [buf][warp][slot 0..15] {a_lo, a_hi, v_lo, v_hi}
    __shared__ __align__(16) float4 sst[2][FWPB][16];

    const int lane = threadIdx.x & 31;
    const int wl   = threadIdx.x >> 5;
    const int b    = blockIdx.x * FWPB + wl;
    if (b >= Bf) return;                     // uniform per warp
    const bool act = lane < Tt;
    const int  j   = act ? lane : 0;
    const int  sp4sh = (lane >> 1) * 4 + (lane & 1);

    float* sw0 = (float*)&sst[0][wl][0];
    float* sw1 = (float*)&sst[1][wl][0];

    // loop-invariant tables: column j of exp(trans)/trans packed over i-pairs
    u64 Ep[NP], Tp[NP];
#pragma unroll
    for (int p = 0; p < NP; p++) {
        const int i0 = 2 * p, i1 = 2 * p + 1;
        float t0 = trans[i0 * Tt + j];
        float t1 = (i1 < Tt) ? trans[i1 * Tt + j] : -1e30f;
        Tp[p] = pack2(t0, t1);
        Ep[p] = pack2(__expf(t0), (i1 < Tt) ? __expf(t1) : 0.f);
    }

    // ---- l = 0 ----
    const size_t emstep = (size_t)Bf * Tt;
    const float* emp = em + (size_t)b * Tt + j;
    float e0 = *emp;  emp += emstep;          // em[0]
    float s0 = start[j] + e0;
    float a = act ? __expf(s0) : 0.f;
    float v = act ? s0 : -1e30f;

    float* gsp = &g_score[(size_t)b * GST + j];
    if (act) *gsp = s0;
    gsp += (size_t)Bf * GST;

    float inv = __shfl_sync(0xffffffffu, rcpa(a), 0);

    // emission pipeline: e_cur = em[1], e_nxt = em[2]
    float e_cur = *emp;  emp += emstep;
    float e_nxt = *emp;  emp += emstep;       // emp -> em[3]
    float ee_cur = __expf(e_cur);
    float logacc2 = 0.f;

    // ---- main loop: 511 steps, unrolled x2 over the double buffer ----
    for (int l = 1; l + 1 < Lf; l += 2) {
        fwd_step(sw0, sp4sh, Ep, Tp, a, v, inv, e_cur, ee_cur,
                 logacc2, act, gsp);
        e_cur = e_nxt; ee_cur = __expf(e_cur);
        if (l + 2 < Lf) { e_nxt = *emp; emp += emstep; }

        fwd_step(sw1, sp4sh, Ep, Tp, a, v, inv, e_cur, ee_cur,
                 logacc2, act, gsp);
        e_cur = e_nxt; ee_cur = __expf(e_cur);
        if (l + 3 < Lf) { e_nxt = *emp; emp += emstep; }
    }
    fwd_step(sw0, sp4sh, Ep, Tp, a, v, inv, e_cur, ee_cur,
             logacc2, act, gsp);              // l = 511

    // logz = ln2*logacc2 + log( sum_i a_final[i] * exp(end[i]) )
    float d = act ? a * __expf(endt[j]) : 0.f;
#pragma unroll
    for (int off = 16; off; off >>= 1) d += __shfl_xor_sync(0xffffffffu, d, off);
    if (lane == 0) g_logz[b] = logacc2 * 0.69314718056f + __logf(d);
}

// ---------------------------------------------------------------------------
__global__ void numer_kernel(const float* __restrict__ em, const int* __restrict__ tags,
                             const float* __restrict__ trans, const float* __restrict__ start,
                             const float* __restrict__ endt)
{
    int idx = blockIdx.x * blockDim.x + threadIdx.x;
    if (idx >= Bf * 32) return;
    int b  = idx & (Bf - 1);
    int c  = idx >> 12;
    int l0 = c * 16;
    float acc = 0.f;
    int prev = 0;
    if (c > 0) prev = tags[(size_t)(l0 - 1) * Bf + b];
#pragma unroll
    for (int dl = 0; dl < 16; dl++) {
        int l  = l0 + dl;
        int tg = tags[(size_t)l * Bf + b];
        acc += em[((size_t)l * Bf + b) * Tt + tg];
        if (l == 0) acc += start[tg];
        else        acc += trans[prev * Tt + tg];
        prev = tg;
    }
    if (l0 + 16 == Lf) acc += endt[prev];
    atomicAdd(&g_num[b], acc);
}

// ---------------------------------------------------------------------------
__device__ __forceinline__ void bt_group(
    const float* __restrict__ em, const float* st, float* out, int base,
    int b, int lane, bool alive, int lbase, int& jn,
    float (&cs)[8], float (&ce)[8], float (&ns)[8], float (&ne)[8], bool load_next)
{
    if (load_next) {
#pragma unroll
        for (int k = 0; k < 8; k++) {
            int l = lbase - 8 - k;
            bool ok = alive && (l >= 0);
            ns[k] = ok ? g_score[((size_t)l * Bf + b) * GST + lane] : 0.f;
            ne[k] = ok ? em[((size_t)(l + 1) * Bf + b) * Tt + lane] : 0.f;
        }
    }
#pragma unroll
    for (int k = 0; k < 8; k++) {
        int l = lbase - k;
        float ej = __shfl_sync(0xffffffffu, ce[k], jn);
        float tt = alive ? (cs[k] + st[lane * Tt + jn]) + ej : -3e38f;
        unsigned uu = ford(tt);
        unsigned mx = __reduce_max_sync(0xffffffffu, uu);
        int j2 = __ffs(__ballot_sync(0xffffffffu, uu == mx)) - 1;
        if (l >= 0) {
            jn = j2;
            if (lane == 0) out[base + (size_t)l * Bf + b] = (float)jn;
        }
    }
}

__global__ __launch_bounds__(256) void backtrack_kernel(
    const float* __restrict__ em, const float* __restrict__ trans,
    const float* __restrict__ endt, float* __restrict__ out, int base)
{
    __shared__ float st[Tt * Tt];
    __shared__ float cpart[8];
    const int tid = threadIdx.x;
    for (int i = tid; i < Tt * Tt; i += 256) st[i] = trans[i];
    __syncthreads();

    const int b    = (blockIdx.x * 256 + tid) >> 5;
    const int lane = tid & 31;
    const bool alive = lane < Tt;

    float sc = alive ? g_score[((size_t)(Lf - 1) * Bf + b) * GST + lane] : -3e38f;
    float t  = alive ? sc + endt[lane] : -3e38f;
    unsigned u  = ford(t);
    unsigned um = __reduce_max_sync(0xffffffffu, u);
    int jn = __ffs(__ballot_sync(0xffffffffu, u == um)) - 1;
    if (lane == 0) out[base + (size_t)(Lf - 1) * Bf + b] = (float)jn;

    float sA[8], eA[8], sB[8], eB[8];
#pragma unroll
    for (int k = 0; k < 8; k++) {
        int l = Lf - 2 - k;
        sA[k] = alive ? g_score[((size_t)l * Bf + b) * GST + lane] : 0.f;
        eA[k] = alive ? em[((size_t)(l + 1) * Bf + b) * Tt + lane] : 0.f;
    }
    for (int g = 0; g < 64; g += 2) {
        bt_group(em, st, out, base, b, lane, alive, Lf - 2 - 8 * g, jn,
                 sA, eA, sB, eB, true);
        bt_group(em, st, out, base, b, lane, alive, Lf - 2 - 8 * (g + 1), jn,
                 sB, eB, sA, eA, g + 1 < 63);
    }

    float c = 0.f;
    if (lane == 0 && base > 0) c = (g_logz[b] - g_num[b]) * (1.0f / Bf);
    if (lane == 0) cpart[tid >> 5] = c;
    __syncthreads();
    if (tid == 0 && base > 0) {
        float sum = 0.f;
#pragma unroll
        for (int w = 0; w < 8; w++) sum += cpart[w];
        atomicAdd(out, sum);
    }
}

// ---------------------------------------------------------------------------
extern "C" void kernel_launch(void* const* d_in, const int* in_sizes, int n_in,
                              void* d_out, int out_size) {
    const float* em    = (const float*)d_in[0];
    const int*   tags  = (const int*)d_in[1];
    const float* trans = (const float*)d_in[2];
    const float* start = (const float*)d_in[3];
    const float* endt  = (const float*)d_in[4];
    float* out = (float*)d_out;

    int base = out_size - Lf * Bf;
    if (base < 0) base = 0;

    init_kernel<<<16, 256>>>(out, base);
    int fblocks = (Bf + FWPB - 1) / FWPB;            // 820
    fwd_vit_kernel<<<fblocks, 32 * FWPB>>>(em, trans, start, endt);
    numer_kernel<<<(Bf * 32) / 256, 256>>>(em, tags, trans, start, endt);
    backtrack_kernel<<<(Bf * 32) / 256, 256>>>(em, trans, endt, out, base);
}

// round 11
// speedup vs baseline: 1.4921x; 1.4921x over previous
#include <cuda_runtime.h>

#define Lf 512
#define Bf 4096
#define Tt 25
#define NP 13      // i-pairs (2p, 2p+1); slot p=12 hi half = pad (i=25)
#define GST 32     // g_score row stride (128B-aligned rows)
#define WPB 2      // warps per block in fwd kernel

__device__ float g_score[(size_t)Lf * Bf * GST];
__device__ float g_logz[Bf];
__device__ float g_num[Bf];

typedef unsigned long long u64;

__device__ __forceinline__ u64 pack2(float lo, float hi) {
    u64 r; asm("mov.b64 %0,{%1,%2};" : "=l"(r) : "f"(lo), "f"(hi)); return r;
}
__device__ __forceinline__ void un2(u64 v, float& a, float& b) {
    asm("mov.b64 {%0,%1},%2;" : "=f"(a), "=f"(b) : "l"(v));
}
__device__ __forceinline__ u64 fma2(u64 a, u64 b, u64 c) {
    u64 d; asm("fma.rn.f32x2 %0,%1,%2,%3;" : "=l"(d) : "l"(a), "l"(b), "l"(c)); return d;
}
__device__ __forceinline__ u64 add2(u64 a, u64 b) {
    u64 d; asm("add.rn.f32x2 %0,%1,%2;" : "=l"(d) : "l"(a), "l"(b)); return d;
}
__device__ __forceinline__ unsigned ford(float f) {
    unsigned v = __float_as_uint(f);
    return (v & 0x80000000u) ? ~v : (v | 0x80000000u);
}
__device__ __forceinline__ float rcpa(float x) {
    float r; asm("rcp.approx.f32 %0, %1;" : "=f"(r) : "f"(x)); return r;
}

// ---------------------------------------------------------------------------
__global__ void init_kernel(float* out, int base) {
    int i = blockIdx.x * blockDim.x + threadIdx.x;
    if (i < Bf) g_num[i] = 0.f;
    if (i == 0 && base > 0) out[0] = 0.f;
}

// ---------------------------------------------------------------------------
// One fused forward+Viterbi step for both chains (R8 smem style: C++ types,
// __syncwarp; normalization/emission-exp off the critical path).
__device__ __forceinline__ void fwd_step(
    float* dA, float* dB,                        // write regions (this buffer)
    const ulonglong2* pA, const ulonglong2* pB,  // read regions  (same buffer)
    int sp, int sh, const u64* Ep, const u64* Tp,
    float& aA, float& vA, float& aB, float& vB,
    float& invA, float& invB,
    float eA, float eB, float eeA, float eeB,
    float& lg2A, float& lg2B,
    bool act, float*& gspA, float*& gspB)
{
    // publish state of previous step in packed layout
    dA[sp * 4 + sh] = aA;  dA[sp * 4 + 2 + sh] = vA;
    dB[sp * 4 + sh] = aB;  dB[sp * 4 + 2 + sh] = vB;
    __syncwarp();

    u64 rAe = 0ull, rAo = 0ull, rBe = 0ull, rBo = 0ull;
    float mA0 = -1e30f, mA1 = -1e30f, mA2 = -1e30f, mA3 = -1e30f;
    float mB0 = -1e30f, mB1 = -1e30f, mB2 = -1e30f, mB3 = -1e30f;
#pragma unroll
    for (int p = 0; p < NP; p++) {
        ulonglong2 sA2 = pA[p];     // {a-pair, v-pair} broadcast LDS.128
        ulonglong2 sB2 = pB[p];
        float sx, sy;
        if (p & 1) {
            rAo = fma2(sA2.x, Ep[p], rAo);
            rBo = fma2(sB2.x, Ep[p], rBo);
            un2(add2(sA2.y, Tp[p]), sx, sy);
            mA2 = fmaxf(mA2, sx); mA3 = fmaxf(mA3, sy);
            un2(add2(sB2.y, Tp[p]), sx, sy);
            mB2 = fmaxf(mB2, sx); mB3 = fmaxf(mB3, sy);
        } else {
            rAe = fma2(sA2.x, Ep[p], rAe);
            rBe = fma2(sB2.x, Ep[p], rBe);
            un2(add2(sA2.y, Tp[p]), sx, sy);
            mA0 = fmaxf(mA0, sx); mA1 = fmaxf(mA1, sy);
            un2(add2(sB2.y, Tp[p]), sx, sy);
            mB0 = fmaxf(mB0, sx); mB1 = fmaxf(mB1, sy);
        }
    }
    float rx, ry;
    un2(add2(rAe, rAo), rx, ry);
    float uA = (rx + ry) * eeA * invA;
    un2(add2(rBe, rBo), rx, ry);
    float uB = (rx + ry) * eeB * invB;
    float svA = fmaxf(fmaxf(mA0, mA1), fmaxf(mA2, mA3)) + eA;  // exact (monotone)
    float svB = fmaxf(fmaxf(mB0, mB1), fmaxf(mB2, mB3)) + eB;

    // account applied scale (off critical path; uniform across lanes)
    lg2A -= __log2f(invA);
    lg2B -= __log2f(invB);

    aA = act ? uA : 0.f;   vA = act ? svA : -1e30f;
    aB = act ? uB : 0.f;   vB = act ? svB : -1e30f;
    if (act) { *gspA = svA; *gspB = svB; }
    gspA += (size_t)Bf * GST; gspB += (size_t)Bf * GST;

    // scale for NEXT step (consumed a full step later -> hidden latency)
    invA = __shfl_sync(0xffffffffu, rcpa(uA), 0);
    invB = __shfl_sync(0xffffffffu, rcpa(uB), 0);
}

// Fused forward + Viterbi: 2 chains per warp, 64-thread blocks (grid 1024 ->
// balanced ~14 warps/SM everywhere).
__global__ __launch_bounds__(32 * WPB) void fwd_vit_kernel(
    const float* __restrict__ em, const float* __restrict__ trans,
    const float* __restrict__ start, const float* __restrict__ endt)
{
    // [buf][warp][chain][slot 0..15][4 floats {a_lo,a_hi,v_lo,v_hi}]
    __shared__ __align__(16) float sst[2][WPB][2][16][4];

    const int lane = threadIdx.x & 31;
    const int wl   = threadIdx.x >> 5;
    const int w    = blockIdx.x * WPB + wl;            // 0..2047
    const int bA   = w;
    const int bB   = w + Bf / 2;
    const bool act = lane < Tt;
    const int  j   = act ? lane : 0;
    const int  sp  = lane >> 1;
    const int  sh  = lane & 1;
    const bool wr  = true;  (void)wr;

    float* dA0 = &sst[0][wl][0][0][0];
    float* dB0 = &sst[0][wl][1][0][0];
    float* dA1 = &sst[1][wl][0][0][0];
    float* dB1 = &sst[1][wl][1][0][0];
    const ulonglong2* pA0 = (const ulonglong2*)dA0;
    const ulonglong2* pB0 = (const ulonglong2*)dB0;
    const ulonglong2* pA1 = (const ulonglong2*)dA1;
    const ulonglong2* pB1 = (const ulonglong2*)dB1;

    // loop-invariant tables
    u64 Ep[NP], Tp[NP];
#pragma unroll
    for (int p = 0; p < NP; p++) {
        const int i0 = 2 * p, i1 = 2 * p + 1;
        float t0 = trans[i0 * Tt + j];
        float t1 = (i1 < Tt) ? trans[i1 * Tt + j] : -1e30f;
        Tp[p] = pack2(t0, t1);
        Ep[p] = pack2(__expf(t0), (i1 < Tt) ? __expf(t1) : 0.f);
    }

    // ---- l = 0 state + emission pipeline ----
    const size_t emstep = (size_t)Bf * Tt;
    const float* empA = em + (size_t)bA * Tt + j;
    const float* empB = em + (size_t)bB * Tt + j;
    float e0A = *empA, e0B = *empB;            // em[0]
    empA += emstep; empB += emstep;
    float eA_cur = *empA, eB_cur = *empB;      // em[1]
    empA += emstep; empB += emstep;
    float eA_nxt = *empA, eB_nxt = *empB;      // em[2]
    empA += emstep; empB += emstep;            // -> em[3]

    const float stj = start[j];
    float s0A = stj + e0A, s0B = stj + e0B;
    float aA = act ? __expf(s0A) : 0.f;
    float vA = act ? s0A : -1e30f;
    float aB = act ? __expf(s0B) : 0.f;
    float vB = act ? s0B : -1e30f;

    float* gspA = &g_score[(size_t)bA * GST + j];
    float* gspB = &g_score[(size_t)bB * GST + j];
    if (act) { *gspA = s0A; *gspB = s0B; }
    gspA += (size_t)Bf * GST; gspB += (size_t)Bf * GST;

    float invA = __shfl_sync(0xffffffffu, rcpa(aA), 0);
    float invB = __shfl_sync(0xffffffffu, rcpa(aB), 0);
    float eeA = __expf(eA_cur);
    float eeB = __expf(eB_cur);
    float lg2A = 0.f, lg2B = 0.f;

    // ---- main loop: 511 steps, unrolled x2 over the double buffer ----
    for (int l = 1; l + 1 < Lf; l += 2) {
        fwd_step(dA0, dB0, pA0, pB0, sp, sh, Ep, Tp, aA, vA, aB, vB,
                 invA, invB, eA_cur, eB_cur, eeA, eeB, lg2A, lg2B,
                 act, gspA, gspB);
        eA_cur = eA_nxt; eB_cur = eB_nxt;
        eeA = __expf(eA_cur); eeB = __expf(eB_cur);
        if (l + 2 < Lf) {
            eA_nxt = *empA; empA += emstep;
            eB_nxt = *empB; empB += emstep;
        }
        fwd_step(dA1, dB1, pA1, pB1, sp, sh, Ep, Tp, aA, vA, aB, vB,
                 invA, invB, eA_cur, eB_cur, eeA, eeB, lg2A, lg2B,
                 act, gspA, gspB);
        eA_cur = eA_nxt; eB_cur = eB_nxt;
        eeA = __expf(eA_cur); eeB = __expf(eB_cur);
        if (l + 3 < Lf) {
            eA_nxt = *empA; empA += emstep;
            eB_nxt = *empB; empB += emstep;
        }
    }
    fwd_step(dA0, dB0, pA0, pB0, sp, sh, Ep, Tp, aA, vA, aB, vB,
             invA, invB, eA_cur, eB_cur, eeA, eeB, lg2A, lg2B,
             act, gspA, gspB);               // l = 511

    // logz = ln2*lg2 + log( sum_i a_final[i] * exp(end[i]) )
    float ee = __expf(endt[j]);
    float dA = act ? aA * ee : 0.f;
    float dB = act ? aB * ee : 0.f;
#pragma unroll
    for (int off = 16; off; off >>= 1) {
        dA += __shfl_xor_sync(0xffffffffu, dA, off);
        dB += __shfl_xor_sync(0xffffffffu, dB, off);
    }
    if (lane == 0) {
        g_logz[bA] = lg2A * 0.69314718056f + __logf(dA);
        g_logz[bB] = lg2B * 0.69314718056f + __logf(dB);
    }
}

// ---------------------------------------------------------------------------
__global__ void numer_kernel(const float* __restrict__ em, const int* __restrict__ tags,
                             const float* __restrict__ trans, const float* __restrict__ start,
                             const float* __restrict__ endt)
{
    int idx = blockIdx.x * blockDim.x + threadIdx.x;
    if (idx >= Bf * 32) return;
    int b  = idx & (Bf - 1);
    int c  = idx >> 12;
    int l0 = c * 16;
    float acc = 0.f;
    int prev = 0;
    if (c > 0) prev = tags[(size_t)(l0 - 1) * Bf + b];
#pragma unroll
    for (int dl = 0; dl < 16; dl++) {
        int l  = l0 + dl;
        int tg = tags[(size_t)l * Bf + b];
        acc += em[((size_t)l * Bf + b) * Tt + tg];
        if (l == 0) acc += start[tg];
        else        acc += trans[prev * Tt + tg];
        prev = tg;
    }
    if (l0 + 16 == Lf) acc += endt[prev];
    atomicAdd(&g_num[b], acc);
}

// ---------------------------------------------------------------------------
__device__ __forceinline__ void bt_group(
    const float* __restrict__ em, const float* st, float* out, int base,
    int b, int lane, bool alive, int lbase, int& jn,
    float (&cs)[8], float (&ce)[8], float (&ns)[8], float (&ne)[8], bool load_next)
{
    if (load_next) {
#pragma unroll
        for (int k = 0; k < 8; k++) {
            int l = lbase - 8 - k;
            bool ok = alive && (l >= 0);
            ns[k] = ok ? g_score[((size_t)l * Bf + b) * GST + lane] : 0.f;
            ne[k] = ok ? em[((size_t)(l + 1) * Bf + b) * Tt + lane] : 0.f;
        }
    }
#pragma unroll
    for (int k = 0; k < 8; k++) {
        int l = lbase - k;
        float ej = __shfl_sync(0xffffffffu, ce[k], jn);
        float tt = alive ? (cs[k] + st[lane * Tt + jn]) + ej : -3e38f;
        unsigned uu = ford(tt);
        unsigned mx = __reduce_max_sync(0xffffffffu, uu);
        int j2 = __ffs(__ballot_sync(0xffffffffu, uu == mx)) - 1;
        if (l >= 0) {
            jn = j2;
            if (lane == 0) out[base + (size_t)l * Bf + b] = (float)jn;
        }
    }
}

__global__ __launch_bounds__(256) void backtrack_kernel(
    const float* __restrict__ em, const float* __restrict__ trans,
    const float* __restrict__ endt, float* __restrict__ out, int base)
{
    __shared__ float st[Tt * Tt];
    __shared__ float cpart[8];
    const int tid = threadIdx.x;
    for (int i = tid; i < Tt * Tt; i += 256) st[i] = trans[i];
    __syncthreads();

    const int b    = (blockIdx.x * 256 + tid) >> 5;
    const int lane = tid & 31;
    const bool alive = lane < Tt;

    float sc = alive ? g_score[((size_t)(Lf - 1) * Bf + b) * GST + lane] : -3e38f;
    float t  = alive ? sc + endt[lane] : -3e38f;
    unsigned u  = ford(t);
    unsigned um = __reduce_max_sync(0xffffffffu, u);
    int jn = __ffs(__ballot_sync(0xffffffffu, u == um)) - 1;
    if (lane == 0) out[base + (size_t)(Lf - 1) * Bf + b] = (float)jn;

    float sA[8], eA[8], sB[8], eB[8];
#pragma unroll
    for (int k = 0; k < 8; k++) {
        int l = Lf - 2 - k;
        sA[k] = alive ? g_score[((size_t)l * Bf + b) * GST + lane] : 0.f;
        eA[k] = alive ? em[((size_t)(l + 1) * Bf + b) * Tt + lane] : 0.f;
    }
    for (int g = 0; g < 64; g += 2) {
        bt_group(em, st, out, base, b, lane, alive, Lf - 2 - 8 * g, jn,
                 sA, eA, sB, eB, true);
        bt_group(em, st, out, base, b, lane, alive, Lf - 2 - 8 * (g + 1), jn,
                 sB, eB, sA, eA, g + 1 < 63);
    }

    float c = 0.f;
    if (lane == 0 && base > 0) c = (g_logz[b] - g_num[b]) * (1.0f / Bf);
    if (lane == 0) cpart[tid >> 5] = c;
    __syncthreads();
    if (tid == 0 && base > 0) {
        float sum = 0.f;
#pragma unroll
        for (int w = 0; w < 8; w++) sum += cpart[w];
        atomicAdd(out, sum);
    }
}

// ---------------------------------------------------------------------------
extern "C" void kernel_launch(void* const* d_in, const int* in_sizes, int n_in,
                              void* d_out, int out_size) {
    const float* em    = (const float*)d_in[0];
    const int*   tags  = (const int*)d_in[1];
    const float* trans = (const float*)d_in[2];
    const float* start = (const float*)d_in[3];
    const float* endt  = (const float*)d_in[4];
    float* out = (float*)d_out;

    int base = out_size - Lf * Bf;
    if (base < 0) base = 0;

    init_kernel<<<16, 256>>>(out, base);
    fwd_vit_kernel<<<Bf / (2 * WPB), 32 * WPB>>>(em, trans, start, endt); // 1024 x 64
    numer_kernel<<<(Bf * 32) / 256, 256>>>(em, tags, trans, start, endt);
    backtrack_kernel<<<(Bf * 32) / 256, 256>>>(em, trans, endt, out, base);
}